// round 2
// baseline (speedup 1.0000x reference)
#include <cuda_runtime.h>

// PLIF spiking neuron forward — round 2: explicit MLP.
// x: [B=16, T=32, C=128, H=32, W=32] fp32; a scalar; out spikes fp32.
//
// Each thread handles TWO independent float4 sites (separated by TOTAL_V4/2,
// so both warps' accesses stay fully coalesced), and the t-loop is unrolled
// by 4 with all 8 loads front-batched -> 8 independent 16B loads in flight
// per thread before any dependent FMA.

constexpr int B = 16;
constexpr int T = 32;
constexpr int C = 128;
constexpr int H = 32;
constexpr int W = 32;
constexpr int CHW_V4   = (C * H * W) / 4;   // 32768 float4 per (b,t) slice
constexpr int TOTAL_V4 = B * CHW_V4;        // 524288 float4 sites
constexpr int HALF_V4  = TOTAL_V4 / 2;      // 262144

__device__ __forceinline__ void plif_step(float4 xi, float decay,
                                          float4& mem, float4& s)
{
    mem.x = fmaf(decay, mem.x, xi.x);
    mem.y = fmaf(decay, mem.y, xi.y);
    mem.z = fmaf(decay, mem.z, xi.z);
    mem.w = fmaf(decay, mem.w, xi.w);

    s.x = (mem.x >= 1.0f) ? 1.0f : 0.0f;
    s.y = (mem.y >= 1.0f) ? 1.0f : 0.0f;
    s.z = (mem.z >= 1.0f) ? 1.0f : 0.0f;
    s.w = (mem.w >= 1.0f) ? 1.0f : 0.0f;

    mem.x = (mem.x >= 1.0f) ? 0.0f : mem.x;
    mem.y = (mem.y >= 1.0f) ? 0.0f : mem.y;
    mem.z = (mem.z >= 1.0f) ? 0.0f : mem.z;
    mem.w = (mem.w >= 1.0f) ? 0.0f : mem.w;
}

__global__ __launch_bounds__(256)
void plif_fwd_kernel(const float4* __restrict__ x,
                     const float*  __restrict__ a,
                     float4*       __restrict__ out)
{
    int i = blockIdx.x * blockDim.x + threadIdx.x;
    if (i >= HALF_V4) return;

    // Stream A: site i (first half of sites); Stream B: site i + HALF_V4.
    int bA   = i / CHW_V4;
    int chwA = i - bA * CHW_V4;
    int baseA = bA * (T * CHW_V4) + chwA;

    int j    = i + HALF_V4;
    int bB   = j / CHW_V4;
    int chwB = j - bB * CHW_V4;
    int baseB = bB * (T * CHW_V4) + chwB;

    float av = __ldg(a);
    float decay = 1.0f / (1.0f + expf(-av));

    float4 memA = make_float4(0.f, 0.f, 0.f, 0.f);
    float4 memB = make_float4(0.f, 0.f, 0.f, 0.f);

    #pragma unroll
    for (int tb = 0; tb < T; tb += 4) {
        // Front-batched loads: 8 independent LDG.128 in flight.
        float4 a0 = __ldcs(&x[baseA + (tb + 0) * CHW_V4]);
        float4 a1 = __ldcs(&x[baseA + (tb + 1) * CHW_V4]);
        float4 a2 = __ldcs(&x[baseA + (tb + 2) * CHW_V4]);
        float4 a3 = __ldcs(&x[baseA + (tb + 3) * CHW_V4]);
        float4 b0 = __ldcs(&x[baseB + (tb + 0) * CHW_V4]);
        float4 b1 = __ldcs(&x[baseB + (tb + 1) * CHW_V4]);
        float4 b2 = __ldcs(&x[baseB + (tb + 2) * CHW_V4]);
        float4 b3 = __ldcs(&x[baseB + (tb + 3) * CHW_V4]);

        float4 s;
        plif_step(a0, decay, memA, s); __stcs(&out[baseA + (tb + 0) * CHW_V4], s);
        plif_step(b0, decay, memB, s); __stcs(&out[baseB + (tb + 0) * CHW_V4], s);
        plif_step(a1, decay, memA, s); __stcs(&out[baseA + (tb + 1) * CHW_V4], s);
        plif_step(b1, decay, memB, s); __stcs(&out[baseB + (tb + 1) * CHW_V4], s);
        plif_step(a2, decay, memA, s); __stcs(&out[baseA + (tb + 2) * CHW_V4], s);
        plif_step(b2, decay, memB, s); __stcs(&out[baseB + (tb + 2) * CHW_V4], s);
        plif_step(a3, decay, memA, s); __stcs(&out[baseA + (tb + 3) * CHW_V4], s);
        plif_step(b3, decay, memB, s); __stcs(&out[baseB + (tb + 3) * CHW_V4], s);
    }
}

extern "C" void kernel_launch(void* const* d_in, const int* in_sizes, int n_in,
                              void* d_out, int out_size)
{
    const float4* x   = (const float4*)d_in[0];
    const float*  a   = (const float*)d_in[1];
    float4*       out = (float4*)d_out;

    constexpr int THREADS = 256;
    constexpr int BLOCKS  = (HALF_V4 + THREADS - 1) / THREADS;  // 1024

    plif_fwd_kernel<<<BLOCKS, THREADS>>>(x, a, out);
}

// round 3
// speedup vs baseline: 1.0109x; 1.0109x over previous
#include <cuda_runtime.h>

// PLIF spiking neuron forward — round 3: phase-bursted R/W.
// x: [B=16, T=32, C=128, H=32, W=32] fp32; a scalar; out spikes fp32 {0,1}.
//
// One float4 site per thread; t-loop unrolled by 8 with strict phasing:
//   LDG.128 x8 (4KB/warp read burst) -> compute x8 -> STG.128 x8 (4KB/warp
//   write burst). Goal: fewer DRAM read<->write bus turnarounds per byte.

constexpr int B = 16;
constexpr int T = 32;
constexpr int C = 128;
constexpr int H = 32;
constexpr int W = 32;
constexpr int CHW_V4   = (C * H * W) / 4;   // 32768 float4 per (b,t) slice
constexpr int TOTAL_V4 = B * CHW_V4;        // 524288 float4 sites
constexpr int UNROLL   = 8;

__global__ __launch_bounds__(256)
void plif_fwd_kernel(const float4* __restrict__ x,
                     const float*  __restrict__ a,
                     float4*       __restrict__ out)
{
    int i = blockIdx.x * blockDim.x + threadIdx.x;
    if (i >= TOTAL_V4) return;

    int b    = i / CHW_V4;
    int chw  = i - b * CHW_V4;
    int base = b * (T * CHW_V4) + chw;

    float av = __ldg(a);
    float decay = 1.0f / (1.0f + expf(-av));

    float mx = 0.0f, my = 0.0f, mz = 0.0f, mw = 0.0f;

    #pragma unroll
    for (int tb = 0; tb < T; tb += UNROLL) {
        float4 xi[UNROLL];
        float4 s[UNROLL];

        // Phase 1: read burst (8 independent LDG.128).
        #pragma unroll
        for (int u = 0; u < UNROLL; u++)
            xi[u] = __ldcs(&x[base + (tb + u) * CHW_V4]);

        // Phase 2: compute (serial recurrence, no memory traffic).
        #pragma unroll
        for (int u = 0; u < UNROLL; u++) {
            mx = fmaf(decay, mx, xi[u].x);
            my = fmaf(decay, my, xi[u].y);
            mz = fmaf(decay, mz, xi[u].z);
            mw = fmaf(decay, mw, xi[u].w);

            s[u].x = (mx >= 1.0f) ? 1.0f : 0.0f;
            s[u].y = (my >= 1.0f) ? 1.0f : 0.0f;
            s[u].z = (mz >= 1.0f) ? 1.0f : 0.0f;
            s[u].w = (mw >= 1.0f) ? 1.0f : 0.0f;

            mx = (mx >= 1.0f) ? 0.0f : mx;
            my = (my >= 1.0f) ? 0.0f : my;
            mz = (mz >= 1.0f) ? 0.0f : mz;
            mw = (mw >= 1.0f) ? 0.0f : mw;
        }

        // Phase 3: write burst (8 back-to-back STG.128).
        #pragma unroll
        for (int u = 0; u < UNROLL; u++)
            __stcs(&out[base + (tb + u) * CHW_V4], s[u]);
    }
}

extern "C" void kernel_launch(void* const* d_in, const int* in_sizes, int n_in,
                              void* d_out, int out_size)
{
    const float4* x   = (const float4*)d_in[0];
    const float*  a   = (const float*)d_in[1];
    float4*       out = (float4*)d_out;

    constexpr int THREADS = 256;
    constexpr int BLOCKS  = (TOTAL_V4 + THREADS - 1) / THREADS;  // 2048

    plif_fwd_kernel<<<BLOCKS, THREADS>>>(x, a, out);
}